// round 8
// baseline (speedup 1.0000x reference)
#include <cuda_runtime.h>
#include <cuda_bf16.h>
#include <math.h>
#include <stdint.h>

#define B_ 2
#define S_ 2048
#define D_ 1024
#define H_ 16
#define DH_ 64
#define F_ 4096
#define NTOK (B_ * S_)   // 4096

// ---------------- scratch (static device globals; no allocation) ----------------
__device__ float g_qkv[(size_t)NTOK * 3 * D_];
__device__ float g_x1[(size_t)NTOK * D_];
__device__ __align__(16) __nv_bfloat16 g_h_hi[(size_t)NTOK * D_];
__device__ __align__(16) __nv_bfloat16 g_h_lo[(size_t)NTOK * D_];
__device__ __align__(16) __nv_bfloat16 g_attn_hi[(size_t)NTOK * D_];
__device__ __align__(16) __nv_bfloat16 g_attn_lo[(size_t)NTOK * D_];
__device__ __align__(16) __nv_bfloat16 g_ffn_hi[(size_t)NTOK * F_];
__device__ __align__(16) __nv_bfloat16 g_ffn_lo[(size_t)NTOK * F_];
__device__ __align__(16) __nv_bfloat16 g_wqkv_hi[(size_t)3 * D_ * D_];
__device__ __align__(16) __nv_bfloat16 g_wqkv_lo[(size_t)3 * D_ * D_];
__device__ __align__(16) __nv_bfloat16 g_wout_hi[(size_t)D_ * D_];
__device__ __align__(16) __nv_bfloat16 g_wout_lo[(size_t)D_ * D_];
__device__ __align__(16) __nv_bfloat16 g_w1_hi[(size_t)F_ * D_];
__device__ __align__(16) __nv_bfloat16 g_w1_lo[(size_t)F_ * D_];
__device__ __align__(16) __nv_bfloat16 g_w2_hi[(size_t)D_ * F_];
__device__ __align__(16) __nv_bfloat16 g_w2_lo[(size_t)D_ * F_];

__device__ __forceinline__ uint32_t smem_u32(const void* p) {
    uint32_t a;
    asm("{ .reg .u64 t; cvta.to.shared.u64 t, %1; cvt.u32.u64 %0, t; }" : "=r"(a) : "l"(p));
    return a;
}

__device__ __forceinline__ uint32_t packsplit(float x, float y, uint32_t& lo) {
    __nv_bfloat162 hp, lp;
    hp.x = __float2bfloat16_rn(x); hp.y = __float2bfloat16_rn(y);
    lp.x = __float2bfloat16_rn(x - __bfloat162float(hp.x));
    lp.y = __float2bfloat16_rn(y - __bfloat162float(hp.y));
    lo = *(uint32_t*)&lp;
    return *(uint32_t*)&hp;
}

// ---------------- weight split: fp32 -> bf16 hi/lo ----------------
__global__ void __launch_bounds__(256) split_kernel(const float* __restrict__ src,
                                                    __nv_bfloat16* __restrict__ hi,
                                                    __nv_bfloat16* __restrict__ lo,
                                                    int n4) {
    int i = blockIdx.x * 256 + threadIdx.x;
    if (i < n4) {
        float4 f = ((const float4*)src)[i];
        uint32_t l0, l1;
        uint32_t h0 = packsplit(f.x, f.y, l0);
        uint32_t h1 = packsplit(f.z, f.w, l1);
        ((uint2*)hi)[i] = make_uint2(h0, h1);
        ((uint2*)lo)[i] = make_uint2(l0, l1);
    }
}

// ---------------- warp/block reduction helpers ----------------
__device__ __forceinline__ float warp_sum(float v) {
#pragma unroll
    for (int o = 16; o > 0; o >>= 1) v += __shfl_xor_sync(0xffffffffu, v, o);
    return v;
}

// ---------------- LayerNorm: fp32 in -> bf16 hi/lo out ----------------
__global__ void __launch_bounds__(256) ln_kernel(const float* __restrict__ in,
                                                 __nv_bfloat16* __restrict__ hi,
                                                 __nv_bfloat16* __restrict__ lo,
                                                 const float* __restrict__ gamma,
                                                 const float* __restrict__ beta) {
    const int row = blockIdx.x;
    const float* x = in + (size_t)row * D_;
    const int tid = threadIdx.x;
    const int lane = tid & 31;
    const int wid = tid >> 5;

    float4 v = *(const float4*)(x + tid * 4);
    float s = v.x + v.y + v.z + v.w;
    __shared__ float red[8];
    s = warp_sum(s);
    if (lane == 0) red[wid] = s;
    __syncthreads();
    if (tid < 32) {
        float t = (lane < 8) ? red[lane] : 0.f;
        t = warp_sum(t);
        if (lane == 0) red[0] = t;
    }
    __syncthreads();
    const float mean = red[0] * (1.f / D_);
    __syncthreads();

    float q = (v.x - mean) * (v.x - mean) + (v.y - mean) * (v.y - mean) +
              (v.z - mean) * (v.z - mean) + (v.w - mean) * (v.w - mean);
    q = warp_sum(q);
    if (lane == 0) red[wid] = q;
    __syncthreads();
    if (tid < 32) {
        float t = (lane < 8) ? red[lane] : 0.f;
        t = warp_sum(t);
        if (lane == 0) red[0] = t;
    }
    __syncthreads();
    const float stdv = sqrtf(red[0] * (1.f / D_));
    const float inv = 1.f / (stdv + 1e-6f);

    float4 g = *(const float4*)(gamma + tid * 4);
    float4 b = *(const float4*)(beta + tid * 4);
    float o0 = g.x * ((v.x - mean) * inv) + b.x;
    float o1 = g.y * ((v.y - mean) * inv) + b.y;
    float o2 = g.z * ((v.z - mean) * inv) + b.z;
    float o3 = g.w * ((v.w - mean) * inv) + b.w;
    uint32_t l0, l1;
    uint32_t h0 = packsplit(o0, o1, l0);
    uint32_t h1 = packsplit(o2, o3, l1);
    size_t off = ((size_t)row * D_ + tid * 4) >> 1;  // in uint units
    ((uint2*)hi)[off >> 1] = make_uint2(h0, h1);
    ((uint2*)lo)[off >> 1] = make_uint2(l0, l1);
}

// ============================================================================
// bf16x3 mma.sync GEMM with pre-split operands + cp.async pipeline.
// C[M,N] = A[M,K] * B[N,K]^T (+epilogue)
// EPI: 0 none->fp32, 1 +res->fp32, 2 +bias+GELU->bf16 hi/lo, 3 +bias+res->fp32
// CTA 128x128, 8 warps (2m x 4n), warp tile 64x32, K-chunk 32, double buffered.
// Tiles: 128 rows x 32 bf16 (64B data, 80B pitch).
// ============================================================================
#define ROWB 80
#define TILEB (128 * ROWB)
#define OFF_ALO (TILEB)
#define OFF_BHI (2 * TILEB)
#define OFF_BLO (3 * TILEB)
#define STAGE_BYTES (4 * TILEB)
#define GEMM_SMEM (2 * STAGE_BYTES)   // 81920

#define LDSM4(r, addr) \
    asm volatile("ldmatrix.sync.aligned.m8n8.x4.shared.b16 {%0,%1,%2,%3}, [%4];" \
                 : "=r"((r)[0]), "=r"((r)[1]), "=r"((r)[2]), "=r"((r)[3]) : "r"(addr))
#define LDSM4T(r, addr) \
    asm volatile("ldmatrix.sync.aligned.m8n8.x4.trans.shared.b16 {%0,%1,%2,%3}, [%4];" \
                 : "=r"((r)[0]), "=r"((r)[1]), "=r"((r)[2]), "=r"((r)[3]) : "r"(addr))
#define MMA_BF16(c, a, b) \
    asm volatile("mma.sync.aligned.m16n8k16.row.col.f32.bf16.bf16.f32 " \
                 "{%0,%1,%2,%3}, {%4,%5,%6,%7}, {%8,%9}, {%0,%1,%2,%3};" \
                 : "+f"((c)[0]), "+f"((c)[1]), "+f"((c)[2]), "+f"((c)[3]) \
                 : "r"((a)[0]), "r"((a)[1]), "r"((a)[2]), "r"((a)[3]), \
                   "r"((b)[0]), "r"((b)[1]))
#define CPASYNC(dst, src) \
    asm volatile("cp.async.ca.shared.global [%0], [%1], 16;" :: "r"(dst), "l"(src))
#define CPCOMMIT() asm volatile("cp.async.commit_group;")
#define CPWAIT0()  asm volatile("cp.async.wait_group 0;")
#define CPWAIT1()  asm volatile("cp.async.wait_group 1;")

__device__ __forceinline__ void copy_stage(uint32_t sdst,
                                           const __nv_bfloat16* __restrict__ Ahi,
                                           const __nv_bfloat16* __restrict__ Alo,
                                           const __nv_bfloat16* __restrict__ Bhi,
                                           const __nv_bfloat16* __restrict__ Blo,
                                           int K, int k0, int tid) {
#pragma unroll
    for (int t = 0; t < 2; t++) {
        int idx = tid + t * 256;          // 0..511
        int r = idx >> 2, c = idx & 3;    // row, 16B chunk
        uint32_t off = (uint32_t)r * ROWB + c * 16;
        size_t g = (size_t)r * K + k0 + c * 8;
        CPASYNC(sdst + off,           Ahi + g);
        CPASYNC(sdst + off + OFF_ALO, Alo + g);
        CPASYNC(sdst + off + OFF_BHI, Bhi + g);
        CPASYNC(sdst + off + OFF_BLO, Blo + g);
    }
}

template <int EPI>
__global__ void __launch_bounds__(256, 1) mma_gemm(int M, int N, int K,
                                                   const __nv_bfloat16* __restrict__ Ahi,
                                                   const __nv_bfloat16* __restrict__ Alo,
                                                   const __nv_bfloat16* __restrict__ Bhi,
                                                   const __nv_bfloat16* __restrict__ Blo,
                                                   float* __restrict__ C,
                                                   __nv_bfloat16* __restrict__ Chi,
                                                   __nv_bfloat16* __restrict__ Clo,
                                                   const float* __restrict__ bias,
                                                   const float* __restrict__ res) {
    extern __shared__ char smem[];
    const uint32_t sb = smem_u32(smem);
    const int tid = threadIdx.x;
    const int wid = tid >> 5;
    const int lane = tid & 31;
    const int warp_m = wid >> 2;
    const int warp_n = wid & 3;

    const size_t arow = (size_t)(blockIdx.y * 128) * K;
    const size_t brow = (size_t)(blockIdx.x * 128) * K;
    const __nv_bfloat16* Ah = Ahi + arow;
    const __nv_bfloat16* Al = Alo + arow;
    const __nv_bfloat16* Bh = Bhi + brow;
    const __nv_bfloat16* Bl = Blo + brow;

    float acc[4][4][4];
#pragma unroll
    for (int i = 0; i < 4; i++)
#pragma unroll
        for (int j = 0; j < 4; j++)
#pragma unroll
            for (int u = 0; u < 4; u++) acc[i][j][u] = 0.f;

    const int nc = K >> 5;

    const int a_lrow = lane & 15;
    const int a_lbyte = (lane >> 4) * 16;
    const int bj = lane >> 3;
    const int b_lrow = (bj >> 1) * 8 + (lane & 7);
    const int b_lbyte = (bj & 1) * 16;

    copy_stage(sb, Ah, Al, Bh, Bl, K, 0, tid);
    CPCOMMIT();

    for (int c = 0; c < nc; c++) {
        const int buf = c & 1;
        const uint32_t st = sb + buf * STAGE_BYTES;

        if (c + 1 < nc) {
            copy_stage(sb + (buf ^ 1) * STAGE_BYTES, Ah, Al, Bh, Bl, K, (c + 1) << 5, tid);
            CPCOMMIT();
            CPWAIT1();
        } else {
            CPWAIT0();
        }
        __syncthreads();

#pragma unroll
        for (int ks = 0; ks < 2; ks++) {
            uint32_t ah[4][4], al[4][4];
#pragma unroll
            for (int mf = 0; mf < 4; mf++) {
                const uint32_t row = warp_m * 64 + mf * 16 + a_lrow;
                const uint32_t addr = st + row * ROWB + ks * 32 + a_lbyte;
                LDSM4(ah[mf], addr);
                LDSM4(al[mf], addr + OFF_ALO);
            }
            uint32_t bh[4][2], bl[4][2];
#pragma unroll
            for (int nf2 = 0; nf2 < 2; nf2++) {
                const uint32_t row = warp_n * 32 + nf2 * 16 + b_lrow;
                const uint32_t addr = st + OFF_BHI + row * ROWB + ks * 32 + b_lbyte;
                uint32_t r[4];
                LDSM4(r, addr);
                bh[nf2 * 2][0] = r[0]; bh[nf2 * 2][1] = r[1];
                bh[nf2 * 2 + 1][0] = r[2]; bh[nf2 * 2 + 1][1] = r[3];
                LDSM4(r, addr + TILEB);
                bl[nf2 * 2][0] = r[0]; bl[nf2 * 2][1] = r[1];
                bl[nf2 * 2 + 1][0] = r[2]; bl[nf2 * 2 + 1][1] = r[3];
            }
#pragma unroll
            for (int mf = 0; mf < 4; mf++)
#pragma unroll
                for (int nf = 0; nf < 4; nf++) {
                    MMA_BF16(acc[mf][nf], ah[mf], bh[nf]);
                    MMA_BF16(acc[mf][nf], ah[mf], bl[nf]);
                    MMA_BF16(acc[mf][nf], al[mf], bh[nf]);
                }
        }
        __syncthreads();
    }

    const int rbase = blockIdx.y * 128 + warp_m * 64 + (lane >> 2);
    const int cbase = blockIdx.x * 128 + warp_n * 32 + (lane & 3) * 2;
#pragma unroll
    for (int mf = 0; mf < 4; mf++) {
#pragma unroll
        for (int h = 0; h < 2; h++) {
            const int row_g = rbase + mf * 16 + h * 8;
            const float* Rrow = (EPI == 1 || EPI == 3) ? res + (size_t)row_g * N : nullptr;
#pragma unroll
            for (int nf = 0; nf < 4; nf++) {
                const int col_g = cbase + nf * 8;
                float t0 = acc[mf][nf][2 * h];
                float t1 = acc[mf][nf][2 * h + 1];
                if (EPI == 2 || EPI == 3) { t0 += bias[col_g]; t1 += bias[col_g + 1]; }
                if (EPI == 2) {
                    t0 = 0.5f * t0 * (1.f + erff(t0 * 0.70710678118654752f));
                    t1 = 0.5f * t1 * (1.f + erff(t1 * 0.70710678118654752f));
                }
                if (EPI == 1 || EPI == 3) { t0 += Rrow[col_g]; t1 += Rrow[col_g + 1]; }
                if (EPI == 2) {
                    uint32_t l;
                    uint32_t hw = packsplit(t0, t1, l);
                    *(uint32_t*)(Chi + (size_t)row_g * N + col_g) = hw;
                    *(uint32_t*)(Clo + (size_t)row_g * N + col_g) = l;
                } else {
                    float2 p; p.x = t0; p.y = t1;
                    *(float2*)(C + (size_t)row_g * N + col_g) = p;
                }
            }
        }
    }
}

// ============================================================================
// MMA flash attention (bf16x3, causal); epilogue emits bf16 hi/lo for Wout GEMM.
// ============================================================================
#define APITCH 144
#define AT_QH 0
#define AT_QL 18432
#define AT_KH 36864
#define AT_KL 46080
#define AT_VH 55296
#define AT_VL 64512
#define AT_SMEM 73728

__device__ __forceinline__ void cvt_store(char* hi, char* lo, uint32_t off, float4 f) {
    uint32_t l0, l1;
    uint32_t h0 = packsplit(f.x, f.y, l0);
    uint32_t h1 = packsplit(f.z, f.w, l1);
    *(uint2*)(hi + off) = make_uint2(h0, h1);
    *(uint2*)(lo + off) = make_uint2(l0, l1);
}

__global__ void __launch_bounds__(128) attn_mma() {
    extern __shared__ char smem[];
    const uint32_t sb = smem_u32(smem);
    const int tid = threadIdx.x;
    const int lane = tid & 31;
    const int wid = tid >> 5;
    const int q0 = blockIdx.x * 128;
    const int hh = blockIdx.y;
    const int bb = blockIdx.z;

#pragma unroll
    for (int i = 0; i < 16; i++) {
        int idx = tid + i * 128;
        int r = idx >> 4, c4 = idx & 15;
        float4 f = *(const float4*)(g_qkv + (size_t)(bb * S_ + q0 + r) * (3 * D_) + hh * DH_ + c4 * 4);
        cvt_store(smem + AT_QH, smem + AT_QL, (uint32_t)r * APITCH + c4 * 8, f);
    }

    float O[2][8][4];
#pragma unroll
    for (int a = 0; a < 2; a++)
#pragma unroll
        for (int b = 0; b < 8; b++)
#pragma unroll
            for (int u = 0; u < 4; u++) O[a][b][u] = 0.f;
    float mrow[2][2] = {{-INFINITY, -INFINITY}, {-INFINITY, -INFINITY}};
    float lrow[2][2] = {{0.f, 0.f}, {0.f, 0.f}};

    const int a_lrow = lane & 15;
    const int a_lbyte = (lane >> 4) * 16;
    const int bj = lane >> 3;
    const int b_lrow = (bj >> 1) * 8 + (lane & 7);
    const int b_lbyte = (bj & 1) * 16;
    const int v_key = (bj & 1) * 8 + (lane & 7);
    const int v_d = (bj >> 1) * 8;

    const int ntiles = blockIdx.x * 2 + 2;
    const int rowmax_warp = q0 + wid * 32 + 31;

    for (int t0 = 0; t0 < ntiles; t0++) {
        const int k0 = t0 * 64;
        __syncthreads();
#pragma unroll
        for (int i = 0; i < 8; i++) {
            int idx = tid + i * 128;
            int r = idx >> 4, c4 = idx & 15;
            const float* kb = g_qkv + (size_t)(bb * S_ + k0 + r) * (3 * D_) + D_ + hh * DH_ + c4 * 4;
            cvt_store(smem + AT_KH, smem + AT_KL, (uint32_t)r * APITCH + c4 * 8, *(const float4*)kb);
            cvt_store(smem + AT_VH, smem + AT_VL, (uint32_t)r * APITCH + c4 * 8, *(const float4*)(kb + D_));
        }
        __syncthreads();
        if (k0 > rowmax_warp) continue;

        float S[2][8][4] = {};
#pragma unroll
        for (int kf = 0; kf < 4; kf++) {
            uint32_t qh[2][4], ql[2][4];
#pragma unroll
            for (int mf = 0; mf < 2; mf++) {
                const uint32_t addr = sb + AT_QH + (uint32_t)(wid * 32 + mf * 16 + a_lrow) * APITCH + kf * 32 + a_lbyte;
                LDSM4(qh[mf], addr);
                LDSM4(ql[mf], addr + (AT_QL - AT_QH));
            }
            uint32_t kh[8][2], kl[8][2];
#pragma unroll
            for (int p = 0; p < 4; p++) {
                const uint32_t addr = sb + AT_KH + (uint32_t)(p * 16 + b_lrow) * APITCH + kf * 32 + b_lbyte;
                uint32_t r4[4];
                LDSM4(r4, addr);
                kh[2 * p][0] = r4[0]; kh[2 * p][1] = r4[1];
                kh[2 * p + 1][0] = r4[2]; kh[2 * p + 1][1] = r4[3];
                LDSM4(r4, addr + (AT_KL - AT_KH));
                kl[2 * p][0] = r4[0]; kl[2 * p][1] = r4[1];
                kl[2 * p + 1][0] = r4[2]; kl[2 * p + 1][1] = r4[3];
            }
#pragma unroll
            for (int mf = 0; mf < 2; mf++)
#pragma unroll
                for (int nf = 0; nf < 8; nf++) {
                    MMA_BF16(S[mf][nf], qh[mf], kh[nf]);
                    MMA_BF16(S[mf][nf], qh[mf], kl[nf]);
                    MMA_BF16(S[mf][nf], ql[mf], kh[nf]);
                }
        }

#pragma unroll
        for (int mf = 0; mf < 2; mf++)
#pragma unroll
            for (int h = 0; h < 2; h++) {
                const int rowg = q0 + wid * 32 + mf * 16 + (lane >> 2) + h * 8;
                float tmax = -INFINITY;
#pragma unroll
                for (int nf = 0; nf < 8; nf++) {
                    const int colg = k0 + nf * 8 + (lane & 3) * 2;
                    float s0 = S[mf][nf][2 * h] * 0.125f;
                    float s1 = S[mf][nf][2 * h + 1] * 0.125f;
                    if (colg > rowg) s0 = -INFINITY;
                    if (colg + 1 > rowg) s1 = -INFINITY;
                    S[mf][nf][2 * h] = s0;
                    S[mf][nf][2 * h + 1] = s1;
                    tmax = fmaxf(tmax, fmaxf(s0, s1));
                }
                tmax = fmaxf(tmax, __shfl_xor_sync(0xffffffffu, tmax, 1));
                tmax = fmaxf(tmax, __shfl_xor_sync(0xffffffffu, tmax, 2));
                const float mn = fmaxf(mrow[mf][h], tmax);
                const float corr = __expf(mrow[mf][h] - mn);
                mrow[mf][h] = mn;
                float ps = 0.f;
#pragma unroll
                for (int nf = 0; nf < 8; nf++) {
                    float p0 = __expf(S[mf][nf][2 * h] - mn);
                    float p1 = __expf(S[mf][nf][2 * h + 1] - mn);
                    S[mf][nf][2 * h] = p0;
                    S[mf][nf][2 * h + 1] = p1;
                    ps += p0 + p1;
                }
                ps += __shfl_xor_sync(0xffffffffu, ps, 1);
                ps += __shfl_xor_sync(0xffffffffu, ps, 2);
                lrow[mf][h] = lrow[mf][h] * corr + ps;
#pragma unroll
                for (int nd = 0; nd < 8; nd++) {
                    O[mf][nd][2 * h] *= corr;
                    O[mf][nd][2 * h + 1] *= corr;
                }
            }

#pragma unroll
        for (int kf = 0; kf < 4; kf++) {
            uint32_t ph[2][4], pl[2][4];
#pragma unroll
            for (int mf = 0; mf < 2; mf++) {
                ph[mf][0] = packsplit(S[mf][2 * kf][0], S[mf][2 * kf][1], pl[mf][0]);
                ph[mf][1] = packsplit(S[mf][2 * kf][2], S[mf][2 * kf][3], pl[mf][1]);
                ph[mf][2] = packsplit(S[mf][2 * kf + 1][0], S[mf][2 * kf + 1][1], pl[mf][2]);
                ph[mf][3] = packsplit(S[mf][2 * kf + 1][2], S[mf][2 * kf + 1][3], pl[mf][3]);
            }
            uint32_t vh[8][2], vl[8][2];
#pragma unroll
            for (int db = 0; db < 4; db++) {
                const uint32_t addr = sb + AT_VH + (uint32_t)(kf * 16 + v_key) * APITCH + (db * 16 + v_d) * 2;
                uint32_t r4[4];
                LDSM4T(r4, addr);
                vh[2 * db][0] = r4[0]; vh[2 * db][1] = r4[1];
                vh[2 * db + 1][0] = r4[2]; vh[2 * db + 1][1] = r4[3];
                LDSM4T(r4, addr + (AT_VL - AT_VH));
                vl[2 * db][0] = r4[0]; vl[2 * db][1] = r4[1];
                vl[2 * db + 1][0] = r4[2]; vl[2 * db + 1][1] = r4[3];
            }
#pragma unroll
            for (int mf = 0; mf < 2; mf++)
#pragma unroll
                for (int nd = 0; nd < 8; nd++) {
                    MMA_BF16(O[mf][nd], ph[mf], vh[nd]);
                    MMA_BF16(O[mf][nd], ph[mf], vl[nd]);
                    MMA_BF16(O[mf][nd], pl[mf], vh[nd]);
                }
        }
    }

    // epilogue: O /= l -> bf16 hi/lo
#pragma unroll
    for (int mf = 0; mf < 2; mf++)
#pragma unroll
        for (int h = 0; h < 2; h++) {
            const float inv = 1.f / lrow[mf][h];
            const int rowg = q0 + wid * 32 + mf * 16 + (lane >> 2) + h * 8;
            const size_t rowoff = (size_t)(bb * S_ + rowg) * D_ + hh * DH_;
#pragma unroll
            for (int nd = 0; nd < 8; nd++) {
                const int col = nd * 8 + (lane & 3) * 2;
                uint32_t l;
                uint32_t hw = packsplit(O[mf][nd][2 * h] * inv, O[mf][nd][2 * h + 1] * inv, l);
                *(uint32_t*)(g_attn_hi + rowoff + col) = hw;
                *(uint32_t*)(g_attn_lo + rowoff + col) = l;
            }
        }
}

// ---------------- launch ----------------
extern "C" void kernel_launch(void* const* d_in, const int* in_sizes, int n_in,
                              void* d_out, int out_size) {
    const float* x = (const float*)d_in[0];
    const float* Wqkv = (const float*)d_in[2];
    const float* Wout = (const float*)d_in[3];
    const float* W1 = (const float*)d_in[4];
    const float* b1 = (const float*)d_in[5];
    const float* W2 = (const float*)d_in[6];
    const float* b2 = (const float*)d_in[7];
    const float* gamma1 = (const float*)d_in[8];
    const float* beta1 = (const float*)d_in[9];
    const float* gamma2 = (const float*)d_in[10];
    const float* beta2 = (const float*)d_in[11];
    float* out = (float*)d_out;

    float *qkv, *x1;
    __nv_bfloat16 *hhi, *hlo, *ahi, *alo, *fhi, *flo;
    __nv_bfloat16 *wqh, *wql, *woh, *wol, *w1h, *w1l, *w2h, *w2l;
    cudaGetSymbolAddress((void**)&qkv, g_qkv);
    cudaGetSymbolAddress((void**)&x1, g_x1);
    cudaGetSymbolAddress((void**)&hhi, g_h_hi);
    cudaGetSymbolAddress((void**)&hlo, g_h_lo);
    cudaGetSymbolAddress((void**)&ahi, g_attn_hi);
    cudaGetSymbolAddress((void**)&alo, g_attn_lo);
    cudaGetSymbolAddress((void**)&fhi, g_ffn_hi);
    cudaGetSymbolAddress((void**)&flo, g_ffn_lo);
    cudaGetSymbolAddress((void**)&wqh, g_wqkv_hi);
    cudaGetSymbolAddress((void**)&wql, g_wqkv_lo);
    cudaGetSymbolAddress((void**)&woh, g_wout_hi);
    cudaGetSymbolAddress((void**)&wol, g_wout_lo);
    cudaGetSymbolAddress((void**)&w1h, g_w1_hi);
    cudaGetSymbolAddress((void**)&w1l, g_w1_lo);
    cudaGetSymbolAddress((void**)&w2h, g_w2_hi);
    cudaGetSymbolAddress((void**)&w2l, g_w2_lo);

    cudaFuncSetAttribute(mma_gemm<0>, cudaFuncAttributeMaxDynamicSharedMemorySize, GEMM_SMEM);
    cudaFuncSetAttribute(mma_gemm<1>, cudaFuncAttributeMaxDynamicSharedMemorySize, GEMM_SMEM);
    cudaFuncSetAttribute(mma_gemm<2>, cudaFuncAttributeMaxDynamicSharedMemorySize, GEMM_SMEM);
    cudaFuncSetAttribute(mma_gemm<3>, cudaFuncAttributeMaxDynamicSharedMemorySize, GEMM_SMEM);
    cudaFuncSetAttribute(attn_mma, cudaFuncAttributeMaxDynamicSharedMemorySize, AT_SMEM);

    // 0) split weights (once per replay; memory-bound)
    split_kernel<<<(3 * D_ * D_ / 4 + 255) / 256, 256>>>(Wqkv, wqh, wql, 3 * D_ * D_ / 4);
    split_kernel<<<(D_ * D_ / 4 + 255) / 256, 256>>>(Wout, woh, wol, D_ * D_ / 4);
    split_kernel<<<(F_ * D_ / 4 + 255) / 256, 256>>>(W1, w1h, w1l, F_ * D_ / 4);
    split_kernel<<<(D_ * F_ / 4 + 255) / 256, 256>>>(W2, w2h, w2l, D_ * F_ / 4);

    // 1) LN1 -> bf16 hi/lo
    ln_kernel<<<NTOK, 256>>>(x, hhi, hlo, gamma1, beta1);
    // 2) QKV projection -> fp32 qkv
    mma_gemm<0><<<dim3(3 * D_ / 128, NTOK / 128), 256, GEMM_SMEM>>>(
        NTOK, 3 * D_, D_, hhi, hlo, wqh, wql, qkv, nullptr, nullptr, nullptr, nullptr);
    // 3) causal flash attention -> bf16 hi/lo
    attn_mma<<<dim3(S_ / 128, H_, B_), 128, AT_SMEM>>>();
    // 4) output projection + residual -> fp32 x1
    mma_gemm<1><<<dim3(D_ / 128, NTOK / 128), 256, GEMM_SMEM>>>(
        NTOK, D_, D_, ahi, alo, woh, wol, x1, nullptr, nullptr, nullptr, x);
    // 5) LN2 -> bf16 hi/lo
    ln_kernel<<<NTOK, 256>>>(x1, hhi, hlo, gamma2, beta2);
    // 6) FFN1 + bias + exact GELU -> bf16 hi/lo
    mma_gemm<2><<<dim3(F_ / 128, NTOK / 128), 256, GEMM_SMEM>>>(
        NTOK, F_, D_, hhi, hlo, w1h, w1l, nullptr, fhi, flo, b1, nullptr);
    // 7) FFN2 + bias + residual -> out (fp32)
    mma_gemm<3><<<dim3(D_ / 128, NTOK / 128), 256, GEMM_SMEM>>>(
        NTOK, D_, F_, fhi, flo, w2h, w2l, out, nullptr, nullptr, b2, x1);
}

// round 10
// speedup vs baseline: 2.6366x; 2.6366x over previous
#include <cuda_runtime.h>
#include <cuda_fp16.h>
#include <math.h>
#include <stdint.h>

#define B_ 2
#define S_ 2048
#define D_ 1024
#define H_ 16
#define DH_ 64
#define F_ 4096
#define NTOK (B_ * S_)   // 4096

// ---------------- scratch (static device globals; no allocation) ----------------
__device__ float g_qkv[(size_t)NTOK * 3 * D_];
__device__ float g_x1[(size_t)NTOK * D_];
__device__ __align__(16) __half g_h[(size_t)NTOK * D_];
__device__ __align__(16) __half g_attn[(size_t)NTOK * D_];
__device__ __align__(16) __half g_ffn[(size_t)NTOK * F_];
__device__ __align__(16) __half g_wqkv[(size_t)3 * D_ * D_];
__device__ __align__(16) __half g_wout[(size_t)D_ * D_];
__device__ __align__(16) __half g_w1[(size_t)F_ * D_];
__device__ __align__(16) __half g_w2[(size_t)D_ * F_];

__device__ __forceinline__ uint32_t smem_u32(const void* p) {
    uint32_t a;
    asm("{ .reg .u64 t; cvta.to.shared.u64 t, %1; cvt.u32.u64 %0, t; }" : "=r"(a) : "l"(p));
    return a;
}

__device__ __forceinline__ uint32_t pack_h2(float x, float y) {
    __half2 h = __floats2half2_rn(x, y);
    return *(uint32_t*)&h;
}

// ---------------- weight convert: fp32 -> fp16 ----------------
__global__ void __launch_bounds__(256) cvt_kernel(const float* __restrict__ src,
                                                  __half* __restrict__ dst, int n4) {
    int i = blockIdx.x * 256 + threadIdx.x;
    if (i < n4) {
        float4 f = ((const float4*)src)[i];
        ((uint2*)dst)[i] = make_uint2(pack_h2(f.x, f.y), pack_h2(f.z, f.w));
    }
}

// ---------------- warp/block reduction helpers ----------------
__device__ __forceinline__ float warp_sum(float v) {
#pragma unroll
    for (int o = 16; o > 0; o >>= 1) v += __shfl_xor_sync(0xffffffffu, v, o);
    return v;
}

// ---------------- LayerNorm: fp32 in -> fp16 out ----------------
__global__ void __launch_bounds__(256) ln_kernel(const float* __restrict__ in,
                                                 __half* __restrict__ out,
                                                 const float* __restrict__ gamma,
                                                 const float* __restrict__ beta) {
    const int row = blockIdx.x;
    const float* x = in + (size_t)row * D_;
    const int tid = threadIdx.x;
    const int lane = tid & 31;
    const int wid = tid >> 5;

    float4 v = *(const float4*)(x + tid * 4);
    float s = v.x + v.y + v.z + v.w;
    __shared__ float red[8];
    s = warp_sum(s);
    if (lane == 0) red[wid] = s;
    __syncthreads();
    if (tid < 32) {
        float t = (lane < 8) ? red[lane] : 0.f;
        t = warp_sum(t);
        if (lane == 0) red[0] = t;
    }
    __syncthreads();
    const float mean = red[0] * (1.f / D_);
    __syncthreads();

    float q = (v.x - mean) * (v.x - mean) + (v.y - mean) * (v.y - mean) +
              (v.z - mean) * (v.z - mean) + (v.w - mean) * (v.w - mean);
    q = warp_sum(q);
    if (lane == 0) red[wid] = q;
    __syncthreads();
    if (tid < 32) {
        float t = (lane < 8) ? red[lane] : 0.f;
        t = warp_sum(t);
        if (lane == 0) red[0] = t;
    }
    __syncthreads();
    const float stdv = sqrtf(red[0] * (1.f / D_));
    const float inv = 1.f / (stdv + 1e-6f);

    float4 g = *(const float4*)(gamma + tid * 4);
    float4 b = *(const float4*)(beta + tid * 4);
    uint2 o;
    o.x = pack_h2(g.x * ((v.x - mean) * inv) + b.x, g.y * ((v.y - mean) * inv) + b.y);
    o.y = pack_h2(g.z * ((v.z - mean) * inv) + b.z, g.w * ((v.w - mean) * inv) + b.w);
    ((uint2*)out)[((size_t)row * D_ + tid * 4) >> 2] = o;
}

// ============================================================================
// fp16 mma.sync GEMM (fp32 accum), cp.async double-buffered.
// C[M,N] = A[M,K] * B[N,K]^T (+epilogue)
// EPI: 0 none->fp32, 1 +res->fp32, 2 +bias+GELU->fp16, 3 +bias+res->fp32
// CTA 128x128, 8 warps (2m x 4n), warp 64x32, K-chunk 64.
// Tile row: 64 fp16 = 128B data, 144B pitch (conflict-free ldmatrix).
// ============================================================================
#define ROWB 144
#define TILEB (128 * ROWB)        // 18432
#define OFF_B TILEB
#define STAGE_BYTES (2 * TILEB)   // 36864
#define GEMM_SMEM (2 * STAGE_BYTES)  // 73728

#define LDSM4(r, addr) \
    asm volatile("ldmatrix.sync.aligned.m8n8.x4.shared.b16 {%0,%1,%2,%3}, [%4];" \
                 : "=r"((r)[0]), "=r"((r)[1]), "=r"((r)[2]), "=r"((r)[3]) : "r"(addr))
#define LDSM4T(r, addr) \
    asm volatile("ldmatrix.sync.aligned.m8n8.x4.trans.shared.b16 {%0,%1,%2,%3}, [%4];" \
                 : "=r"((r)[0]), "=r"((r)[1]), "=r"((r)[2]), "=r"((r)[3]) : "r"(addr))
#define MMA_F16(c, a, b) \
    asm volatile("mma.sync.aligned.m16n8k16.row.col.f32.f16.f16.f32 " \
                 "{%0,%1,%2,%3}, {%4,%5,%6,%7}, {%8,%9}, {%0,%1,%2,%3};" \
                 : "+f"((c)[0]), "+f"((c)[1]), "+f"((c)[2]), "+f"((c)[3]) \
                 : "r"((a)[0]), "r"((a)[1]), "r"((a)[2]), "r"((a)[3]), \
                   "r"((b)[0]), "r"((b)[1]))
#define CPASYNC(dst, src) \
    asm volatile("cp.async.ca.shared.global [%0], [%1], 16;" :: "r"(dst), "l"(src))
#define CPCOMMIT() asm volatile("cp.async.commit_group;")
#define CPWAIT0()  asm volatile("cp.async.wait_group 0;")
#define CPWAIT1()  asm volatile("cp.async.wait_group 1;")

__device__ __forceinline__ void copy_stage(uint32_t sdst,
                                           const __half* __restrict__ A,
                                           const __half* __restrict__ B,
                                           int K, int k0, int tid) {
#pragma unroll
    for (int t = 0; t < 4; t++) {
        int idx = tid + t * 256;          // 0..1023
        int r = idx >> 3, c = idx & 7;    // row, 16B chunk (8 fp16)
        uint32_t off = (uint32_t)r * ROWB + c * 16;
        size_t g = (size_t)r * K + k0 + c * 8;
        CPASYNC(sdst + off,         A + g);
        CPASYNC(sdst + off + OFF_B, B + g);
    }
}

template <int EPI>
__global__ void __launch_bounds__(256) mma_gemm(int M, int N, int K,
                                                const __half* __restrict__ A,
                                                const __half* __restrict__ B,
                                                float* __restrict__ C,
                                                __half* __restrict__ Ch,
                                                const float* __restrict__ bias,
                                                const float* __restrict__ res) {
    extern __shared__ char smem[];
    const uint32_t sb = smem_u32(smem);
    const int tid = threadIdx.x;
    const int wid = tid >> 5;
    const int lane = tid & 31;
    const int warp_m = wid >> 2;
    const int warp_n = wid & 3;

    const __half* Ab = A + (size_t)(blockIdx.y * 128) * K;
    const __half* Bb = B + (size_t)(blockIdx.x * 128) * K;

    float acc[4][4][4];
#pragma unroll
    for (int i = 0; i < 4; i++)
#pragma unroll
        for (int j = 0; j < 4; j++)
#pragma unroll
            for (int u = 0; u < 4; u++) acc[i][j][u] = 0.f;

    const int nc = K >> 6;   // K / 64

    const int a_lrow = lane & 15;
    const int a_lbyte = (lane >> 4) * 16;
    const int bj = lane >> 3;
    const int b_lrow = (bj >> 1) * 8 + (lane & 7);
    const int b_lbyte = (bj & 1) * 16;

    copy_stage(sb, Ab, Bb, K, 0, tid);
    CPCOMMIT();

    for (int c = 0; c < nc; c++) {
        const int buf = c & 1;
        const uint32_t st = sb + buf * STAGE_BYTES;

        if (c + 1 < nc) {
            copy_stage(sb + (buf ^ 1) * STAGE_BYTES, Ab, Bb, K, (c + 1) << 6, tid);
            CPCOMMIT();
            CPWAIT1();
        } else {
            CPWAIT0();
        }
        __syncthreads();

#pragma unroll
        for (int ks = 0; ks < 4; ks++) {
            uint32_t af[4][4];
#pragma unroll
            for (int mf = 0; mf < 4; mf++) {
                const uint32_t row = warp_m * 64 + mf * 16 + a_lrow;
                LDSM4(af[mf], st + row * ROWB + ks * 32 + a_lbyte);
            }
            uint32_t bf[4][2];
#pragma unroll
            for (int nf2 = 0; nf2 < 2; nf2++) {
                const uint32_t row = warp_n * 32 + nf2 * 16 + b_lrow;
                uint32_t r[4];
                LDSM4(r, st + OFF_B + row * ROWB + ks * 32 + b_lbyte);
                bf[nf2 * 2][0] = r[0]; bf[nf2 * 2][1] = r[1];
                bf[nf2 * 2 + 1][0] = r[2]; bf[nf2 * 2 + 1][1] = r[3];
            }
#pragma unroll
            for (int mf = 0; mf < 4; mf++)
#pragma unroll
                for (int nf = 0; nf < 4; nf++)
                    MMA_F16(acc[mf][nf], af[mf], bf[nf]);
        }
        __syncthreads();
    }

    const int rbase = blockIdx.y * 128 + warp_m * 64 + (lane >> 2);
    const int cbase = blockIdx.x * 128 + warp_n * 32 + (lane & 3) * 2;
#pragma unroll
    for (int mf = 0; mf < 4; mf++) {
#pragma unroll
        for (int h = 0; h < 2; h++) {
            const int row_g = rbase + mf * 16 + h * 8;
            const float* Rrow = (EPI == 1 || EPI == 3) ? res + (size_t)row_g * N : nullptr;
#pragma unroll
            for (int nf = 0; nf < 4; nf++) {
                const int col_g = cbase + nf * 8;
                float t0 = acc[mf][nf][2 * h];
                float t1 = acc[mf][nf][2 * h + 1];
                if (EPI == 2 || EPI == 3) { t0 += bias[col_g]; t1 += bias[col_g + 1]; }
                if (EPI == 2) {
                    t0 = 0.5f * t0 * (1.f + erff(t0 * 0.70710678118654752f));
                    t1 = 0.5f * t1 * (1.f + erff(t1 * 0.70710678118654752f));
                }
                if (EPI == 1 || EPI == 3) { t0 += Rrow[col_g]; t1 += Rrow[col_g + 1]; }
                if (EPI == 2) {
                    *(uint32_t*)(Ch + (size_t)row_g * N + col_g) = pack_h2(t0, t1);
                } else {
                    float2 p; p.x = t0; p.y = t1;
                    *(float2*)(C + (size_t)row_g * N + col_g) = p;
                }
            }
        }
    }
}

// ============================================================================
// MMA flash attention (fp16, fp32 accum + fp32 softmax, causal).
// 128 threads = 4 warps, warp = 32 q-rows. Epilogue emits fp16 for Wout GEMM.
// ============================================================================
#define APITCH 144
#define AT_Q 0
#define AT_K 18432
#define AT_V 27648
#define AT_SMEM 36864

__device__ __forceinline__ void cvt_store_h(char* dst, uint32_t off, float4 f) {
    *(uint2*)(dst + off) = make_uint2(pack_h2(f.x, f.y), pack_h2(f.z, f.w));
}

__global__ void __launch_bounds__(128) attn_mma() {
    extern __shared__ char smem[];
    const uint32_t sb = smem_u32(smem);
    const int tid = threadIdx.x;
    const int lane = tid & 31;
    const int wid = tid >> 5;
    const int q0 = blockIdx.x * 128;
    const int hh = blockIdx.y;
    const int bb = blockIdx.z;

#pragma unroll
    for (int i = 0; i < 16; i++) {
        int idx = tid + i * 128;
        int r = idx >> 4, c4 = idx & 15;
        float4 f = *(const float4*)(g_qkv + (size_t)(bb * S_ + q0 + r) * (3 * D_) + hh * DH_ + c4 * 4);
        cvt_store_h(smem + AT_Q, (uint32_t)r * APITCH + c4 * 8, f);
    }

    float O[2][8][4];
#pragma unroll
    for (int a = 0; a < 2; a++)
#pragma unroll
        for (int b = 0; b < 8; b++)
#pragma unroll
            for (int u = 0; u < 4; u++) O[a][b][u] = 0.f;
    float mrow[2][2] = {{-INFINITY, -INFINITY}, {-INFINITY, -INFINITY}};
    float lrow[2][2] = {{0.f, 0.f}, {0.f, 0.f}};

    const int a_lrow = lane & 15;
    const int a_lbyte = (lane >> 4) * 16;
    const int bj = lane >> 3;
    const int b_lrow = (bj >> 1) * 8 + (lane & 7);
    const int b_lbyte = (bj & 1) * 16;
    const int v_key = (bj & 1) * 8 + (lane & 7);
    const int v_d = (bj >> 1) * 8;

    const int ntiles = blockIdx.x * 2 + 2;
    const int rowmax_warp = q0 + wid * 32 + 31;

    for (int t0 = 0; t0 < ntiles; t0++) {
        const int k0 = t0 * 64;
        __syncthreads();
#pragma unroll
        for (int i = 0; i < 8; i++) {
            int idx = tid + i * 128;
            int r = idx >> 4, c4 = idx & 15;
            const float* kb = g_qkv + (size_t)(bb * S_ + k0 + r) * (3 * D_) + D_ + hh * DH_ + c4 * 4;
            cvt_store_h(smem + AT_K, (uint32_t)r * APITCH + c4 * 8, *(const float4*)kb);
            cvt_store_h(smem + AT_V, (uint32_t)r * APITCH + c4 * 8, *(const float4*)(kb + D_));
        }
        __syncthreads();
        if (k0 > rowmax_warp) continue;

        float S[2][8][4] = {};
#pragma unroll
        for (int kf = 0; kf < 4; kf++) {
            uint32_t qf[2][4];
#pragma unroll
            for (int mf = 0; mf < 2; mf++) {
                LDSM4(qf[mf], sb + AT_Q + (uint32_t)(wid * 32 + mf * 16 + a_lrow) * APITCH + kf * 32 + a_lbyte);
            }
            uint32_t kfr[8][2];
#pragma unroll
            for (int p = 0; p < 4; p++) {
                uint32_t r4[4];
                LDSM4(r4, sb + AT_K + (uint32_t)(p * 16 + b_lrow) * APITCH + kf * 32 + b_lbyte);
                kfr[2 * p][0] = r4[0]; kfr[2 * p][1] = r4[1];
                kfr[2 * p + 1][0] = r4[2]; kfr[2 * p + 1][1] = r4[3];
            }
#pragma unroll
            for (int mf = 0; mf < 2; mf++)
#pragma unroll
                for (int nf = 0; nf < 8; nf++)
                    MMA_F16(S[mf][nf], qf[mf], kfr[nf]);
        }

#pragma unroll
        for (int mf = 0; mf < 2; mf++)
#pragma unroll
            for (int h = 0; h < 2; h++) {
                const int rowg = q0 + wid * 32 + mf * 16 + (lane >> 2) + h * 8;
                float tmax = -INFINITY;
#pragma unroll
                for (int nf = 0; nf < 8; nf++) {
                    const int colg = k0 + nf * 8 + (lane & 3) * 2;
                    float s0 = S[mf][nf][2 * h] * 0.125f;
                    float s1 = S[mf][nf][2 * h + 1] * 0.125f;
                    if (colg > rowg) s0 = -INFINITY;
                    if (colg + 1 > rowg) s1 = -INFINITY;
                    S[mf][nf][2 * h] = s0;
                    S[mf][nf][2 * h + 1] = s1;
                    tmax = fmaxf(tmax, fmaxf(s0, s1));
                }
                tmax = fmaxf(tmax, __shfl_xor_sync(0xffffffffu, tmax, 1));
                tmax = fmaxf(tmax, __shfl_xor_sync(0xffffffffu, tmax, 2));
                const float mn = fmaxf(mrow[mf][h], tmax);
                const float corr = __expf(mrow[mf][h] - mn);
                mrow[mf][h] = mn;
                float ps = 0.f;
#pragma unroll
                for (int nf = 0; nf < 8; nf++) {
                    float p0 = __expf(S[mf][nf][2 * h] - mn);
                    float p1 = __expf(S[mf][nf][2 * h + 1] - mn);
                    S[mf][nf][2 * h] = p0;
                    S[mf][nf][2 * h + 1] = p1;
                    ps += p0 + p1;
                }
                ps += __shfl_xor_sync(0xffffffffu, ps, 1);
                ps += __shfl_xor_sync(0xffffffffu, ps, 2);
                lrow[mf][h] = lrow[mf][h] * corr + ps;
#pragma unroll
                for (int nd = 0; nd < 8; nd++) {
                    O[mf][nd][2 * h] *= corr;
                    O[mf][nd][2 * h + 1] *= corr;
                }
            }

#pragma unroll
        for (int kf = 0; kf < 4; kf++) {
            uint32_t pf[2][4];
#pragma unroll
            for (int mf = 0; mf < 2; mf++) {
                pf[mf][0] = pack_h2(S[mf][2 * kf][0], S[mf][2 * kf][1]);
                pf[mf][1] = pack_h2(S[mf][2 * kf][2], S[mf][2 * kf][3]);
                pf[mf][2] = pack_h2(S[mf][2 * kf + 1][0], S[mf][2 * kf + 1][1]);
                pf[mf][3] = pack_h2(S[mf][2 * kf + 1][2], S[mf][2 * kf + 1][3]);
            }
            uint32_t vf[8][2];
#pragma unroll
            for (int db = 0; db < 4; db++) {
                uint32_t r4[4];
                LDSM4T(r4, sb + AT_V + (uint32_t)(kf * 16 + v_key) * APITCH + (db * 16 + v_d) * 2);
                vf[2 * db][0] = r4[0]; vf[2 * db][1] = r4[1];
                vf[2 * db + 1][0] = r4[2]; vf[2 * db + 1][1] = r4[3];
            }
#pragma unroll
            for (int mf = 0; mf < 2; mf++)
#pragma unroll
                for (int nd = 0; nd < 8; nd++)
                    MMA_F16(O[mf][nd], pf[mf], vf[nd]);
        }
    }

    // epilogue: O /= l -> fp16
#pragma unroll
    for (int mf = 0; mf < 2; mf++)
#pragma unroll
        for (int h = 0; h < 2; h++) {
            const float inv = 1.f / lrow[mf][h];
            const int rowg = q0 + wid * 32 + mf * 16 + (lane >> 2) + h * 8;
            const size_t rowoff = (size_t)(bb * S_ + rowg) * D_ + hh * DH_;
#pragma unroll
            for (int nd = 0; nd < 8; nd++) {
                const int col = nd * 8 + (lane & 3) * 2;
                *(uint32_t*)(g_attn + rowoff + col) =
                    pack_h2(O[mf][nd][2 * h] * inv, O[mf][nd][2 * h + 1] * inv);
            }
        }
}

// ---------------- launch ----------------
extern "C" void kernel_launch(void* const* d_in, const int* in_sizes, int n_in,
                              void* d_out, int out_size) {
    const float* x = (const float*)d_in[0];
    const float* Wqkv = (const float*)d_in[2];
    const float* Wout = (const float*)d_in[3];
    const float* W1 = (const float*)d_in[4];
    const float* b1 = (const float*)d_in[5];
    const float* W2 = (const float*)d_in[6];
    const float* b2 = (const float*)d_in[7];
    const float* gamma1 = (const float*)d_in[8];
    const float* beta1 = (const float*)d_in[9];
    const float* gamma2 = (const float*)d_in[10];
    const float* beta2 = (const float*)d_in[11];
    float* out = (float*)d_out;

    float *qkv, *x1;
    __half *h, *attn, *ffn, *wq, *wo, *w1, *w2;
    cudaGetSymbolAddress((void**)&qkv, g_qkv);
    cudaGetSymbolAddress((void**)&x1, g_x1);
    cudaGetSymbolAddress((void**)&h, g_h);
    cudaGetSymbolAddress((void**)&attn, g_attn);
    cudaGetSymbolAddress((void**)&ffn, g_ffn);
    cudaGetSymbolAddress((void**)&wq, g_wqkv);
    cudaGetSymbolAddress((void**)&wo, g_wout);
    cudaGetSymbolAddress((void**)&w1, g_w1);
    cudaGetSymbolAddress((void**)&w2, g_w2);

    cudaFuncSetAttribute(mma_gemm<0>, cudaFuncAttributeMaxDynamicSharedMemorySize, GEMM_SMEM);
    cudaFuncSetAttribute(mma_gemm<1>, cudaFuncAttributeMaxDynamicSharedMemorySize, GEMM_SMEM);
    cudaFuncSetAttribute(mma_gemm<2>, cudaFuncAttributeMaxDynamicSharedMemorySize, GEMM_SMEM);
    cudaFuncSetAttribute(mma_gemm<3>, cudaFuncAttributeMaxDynamicSharedMemorySize, GEMM_SMEM);
    cudaFuncSetAttribute(attn_mma, cudaFuncAttributeMaxDynamicSharedMemorySize, AT_SMEM);

    // 0) convert weights fp32 -> fp16
    cvt_kernel<<<(3 * D_ * D_ / 4 + 255) / 256, 256>>>(Wqkv, wq, 3 * D_ * D_ / 4);
    cvt_kernel<<<(D_ * D_ / 4 + 255) / 256, 256>>>(Wout, wo, D_ * D_ / 4);
    cvt_kernel<<<(F_ * D_ / 4 + 255) / 256, 256>>>(W1, w1, F_ * D_ / 4);
    cvt_kernel<<<(D_ * F_ / 4 + 255) / 256, 256>>>(W2, w2, D_ * F_ / 4);

    // 1) LN1 -> fp16
    ln_kernel<<<NTOK, 256>>>(x, h, gamma1, beta1);
    // 2) QKV projection -> fp32 qkv
    mma_gemm<0><<<dim3(3 * D_ / 128, NTOK / 128), 256, GEMM_SMEM>>>(
        NTOK, 3 * D_, D_, h, wq, qkv, nullptr, nullptr, nullptr);
    // 3) causal flash attention -> fp16
    attn_mma<<<dim3(S_ / 128, H_, B_), 128, AT_SMEM>>>();
    // 4) output projection + residual -> fp32 x1
    mma_gemm<1><<<dim3(D_ / 128, NTOK / 128), 256, GEMM_SMEM>>>(
        NTOK, D_, D_, attn, wo, x1, nullptr, nullptr, x);
    // 5) LN2 -> fp16
    ln_kernel<<<NTOK, 256>>>(x1, h, gamma2, beta2);
    // 6) FFN1 + bias + exact GELU -> fp16
    mma_gemm<2><<<dim3(F_ / 128, NTOK / 128), 256, GEMM_SMEM>>>(
        NTOK, F_, D_, h, w1, nullptr, ffn, b1, nullptr);
    // 7) FFN2 + bias + residual -> out (fp32)
    mma_gemm<3><<<dim3(D_ / 128, NTOK / 128), 256, GEMM_SMEM>>>(
        NTOK, D_, F_, ffn, w2, out, nullptr, b2, x1);
}